// round 2
// baseline (speedup 1.0000x reference)
#include <cuda_runtime.h>
#include <cuda_bf16.h>
#include <cstdint>

// Problem constants
#define NP 16384
#define NG 16384
#define NY 8              // gt segments (grid.y)
#define SEG (NG / NY)     // 2048 gt per block
#define TILE 128
#define NT (SEG / TILE)   // 16 gt tiles per block

#define INF_BITS 0x7f800000u
#define FLT_BIG 3.402823466e38f

// Scratch (device globals — no allocation allowed)
__device__ unsigned int g_min_pred[NP];
__device__ unsigned int g_min_gt[NG];
__device__ float g_part[32][4];

// ---------------------------------------------------------------------------
// Kernel 1: init minima to +inf
// ---------------------------------------------------------------------------
__global__ void k_init() {
    int i = blockIdx.x * blockDim.x + threadIdx.x;
    if (i < NP) g_min_pred[i] = INF_BITS;
    if (i < NG) g_min_gt[i]   = INF_BITS;
}

// ---------------------------------------------------------------------------
// Kernel 2: fused tiled pairwise-min.
// Block: 256 threads (tx in [0,16) over gt, ty in [0,16) over pred).
// Each thread: 8 pred rows (ty+16i) x 8 gt cols (tx+16j) register tile.
// Row mins (pred side) persist in registers across all NT gt tiles.
// Col mins (gt side) reduced through shared memory per tile -> atomicMin.
// ---------------------------------------------------------------------------
__global__ __launch_bounds__(256, 2)
void k_pairs(const float* __restrict__ pp, const float* __restrict__ gp) {
    __shared__ float4 sp[TILE];
    __shared__ float4 sg[TILE];
    __shared__ float  sred[TILE * 17];   // padded (pitch 17) reduction buffer

    const int tid = threadIdx.x;
    const int tx = tid & 15;
    const int ty = tid >> 4;
    const int bx = blockIdx.x;   // pred tile index (0..127)
    const int by = blockIdx.y;   // gt segment index (0..NY-1)

    // Stage pred tile (x, y, z, |p|^2)
    if (tid < TILE) {
        int idx = bx * TILE + tid;
        float x = pp[3 * idx + 0];
        float y = pp[3 * idx + 1];
        float z = pp[3 * idx + 2];
        sp[tid] = make_float4(x, y, z, x * x + y * y + z * z);
    }
    __syncthreads();

    float px[8], py[8], pz[8], pq[8], rmin[8];
#pragma unroll
    for (int i = 0; i < 8; i++) {
        float4 v = sp[ty + 16 * i];
        px[i] = v.x; py[i] = v.y; pz[i] = v.z; pq[i] = v.w;
        rmin[i] = FLT_BIG;
    }

    for (int t = 0; t < NT; t++) {
        __syncthreads();   // sg rewrite + sred reuse safe
        if (tid < TILE) {
            int idx = by * SEG + t * TILE + tid;
            float x = gp[3 * idx + 0];
            float y = gp[3 * idx + 1];
            float z = gp[3 * idx + 2];
            sg[tid] = make_float4(x, y, z, x * x + y * y + z * z);
        }
        __syncthreads();

        float gx[8], gy[8], gz[8], gq[8], cmin[8];
#pragma unroll
        for (int j = 0; j < 8; j++) {
            float4 v = sg[tx + 16 * j];
            gx[j] = v.x; gy[j] = v.y; gz[j] = v.z; gq[j] = v.w;
            cmin[j] = FLT_BIG;
        }

#pragma unroll
        for (int i = 0; i < 8; i++) {
#pragma unroll
            for (int j = 0; j < 8; j++) {
                float d = px[i] * gx[j];
                d = fmaf(py[i], gy[j], d);
                d = fmaf(pz[i], gz[j], d);
                float v = fmaf(d, -2.0f, pq[i] + gq[j]);
                v = fmaxf(v, 0.0f);            // clamp (monotone w.r.t. min)
                rmin[i] = fminf(rmin[i], v);
                cmin[j] = fminf(cmin[j], v);
            }
        }

        // Column (gt) reduction across ty for this tile
#pragma unroll
        for (int j = 0; j < 8; j++)
            sred[(tx + 16 * j) * 17 + ty] = cmin[j];
        __syncthreads();
        if (tid < TILE) {
            float m = sred[tid * 17];
#pragma unroll
            for (int k = 1; k < 16; k++) m = fminf(m, sred[tid * 17 + k]);
            atomicMin(&g_min_gt[by * SEG + t * TILE + tid], __float_as_uint(m));
        }
    }

    // Row (pred) reduction across tx, once per block
    __syncthreads();
#pragma unroll
    for (int i = 0; i < 8; i++)
        sred[(ty + 16 * i) * 17 + tx] = rmin[i];
    __syncthreads();
    if (tid < TILE) {
        float m = sred[tid * 17];
#pragma unroll
        for (int k = 1; k < 16; k++) m = fminf(m, sred[tid * 17 + k]);
        atomicMin(&g_min_pred[bx * TILE + tid], __float_as_uint(m));
    }
}

// ---------------------------------------------------------------------------
// Kernel 3: per-block weighted partial sums (deterministic layout).
// 32 blocks x 256 threads; block b handles slice [b*512, (b+1)*512) of both.
// ---------------------------------------------------------------------------
__global__ void k_wsum(const float* __restrict__ wp, const float* __restrict__ wg) {
    __shared__ float sh[4][8];
    const int b = blockIdx.x;
    const int tid = threadIdx.x;
    const int lane = tid & 31;
    const int wid = tid >> 5;

    float a0 = 0.f, a1 = 0.f, a2 = 0.f, a3 = 0.f;
#pragma unroll
    for (int k = 0; k < 2; k++) {
        int i = b * 512 + k * 256 + tid;
        float w  = wp[i];
        float m  = fmaxf(__uint_as_float(g_min_pred[i]), 0.0f);
        a0 += w * m;  a1 += w;
        float w2 = wg[i];
        float m2 = fmaxf(__uint_as_float(g_min_gt[i]), 0.0f);
        a2 += w2 * m2; a3 += w2;
    }
#pragma unroll
    for (int o = 16; o > 0; o >>= 1) {
        a0 += __shfl_down_sync(0xffffffffu, a0, o);
        a1 += __shfl_down_sync(0xffffffffu, a1, o);
        a2 += __shfl_down_sync(0xffffffffu, a2, o);
        a3 += __shfl_down_sync(0xffffffffu, a3, o);
    }
    if (lane == 0) { sh[0][wid] = a0; sh[1][wid] = a1; sh[2][wid] = a2; sh[3][wid] = a3; }
    __syncthreads();
    if (tid == 0) {
        float t0 = 0.f, t1 = 0.f, t2 = 0.f, t3 = 0.f;
#pragma unroll
        for (int w = 0; w < 8; w++) { t0 += sh[0][w]; t1 += sh[1][w]; t2 += sh[2][w]; t3 += sh[3][w]; }
        g_part[b][0] = t0; g_part[b][1] = t1; g_part[b][2] = t2; g_part[b][3] = t3;
    }
}

// ---------------------------------------------------------------------------
// Kernel 4: final fixed-order combine
// ---------------------------------------------------------------------------
__global__ void k_final(float* __restrict__ out) {
    if (threadIdx.x == 0 && blockIdx.x == 0) {
        float s0 = 0.f, s1 = 0.f, s2 = 0.f, s3 = 0.f;
        for (int b = 0; b < 32; b++) {
            s0 += g_part[b][0]; s1 += g_part[b][1];
            s2 += g_part[b][2]; s3 += g_part[b][3];
        }
        out[0] = s0 / fmaxf(s1, 1e-9f) + s2 / fmaxf(s3, 1e-9f);
    }
}

// ---------------------------------------------------------------------------
extern "C" void kernel_launch(void* const* d_in, const int* in_sizes, int n_in,
                              void* d_out, int out_size) {
    const float* pred = (const float*)d_in[0];   // (P,3)
    const float* gt   = (const float*)d_in[1];   // (G,3)
    const float* wp   = (const float*)d_in[2];   // (P,)
    const float* wg   = (const float*)d_in[3];   // (G,)
    float* out = (float*)d_out;

    k_init<<<NP / 256, 256>>>();
    dim3 grid(NP / TILE, NY);
    k_pairs<<<grid, 256>>>(pred, gt);
    k_wsum<<<32, 256>>>(wp, wg);
    k_final<<<1, 32>>>(out);
}